// round 11
// baseline (speedup 1.0000x reference)
#include <cuda_runtime.h>
#include <cuda_bf16.h>
#include <math.h>
#include <stdint.h>

#define T_ 512
#define B_ 64
#define I_ 1024
#define H_ 1024
#define L_ 2
#define BH (B_*H_)
#define RCTAS 64

typedef __nv_bfloat16 bf16;

// ---------------- static device scratch ----------------
__device__ __align__(256) float g_gx[(size_t)3*L_*T_*B_*H_];
__device__ __align__(256) bf16 g_Whi[(size_t)3*L_*H_*I_], g_Wlo[(size_t)3*L_*H_*I_];
__device__ __align__(256) bf16 g_Uhi[(size_t)3*L_*H_*H_], g_Ulo[(size_t)3*L_*H_*H_];
__device__ __align__(256) bf16 g_xhi[(size_t)T_*B_*I_], g_xlo[(size_t)T_*B_*I_];
__device__ __align__(256) float g_h[2][L_*BH];
__device__ __align__(256) bf16 g_hhi[2][L_*BH], g_hlo[2][L_*BH];
__device__ __align__(256) float g_z[L_*BH];
__device__ __align__(256) bf16 g_rhhi[L_*BH], g_rhlo[L_*BH];
__device__ unsigned g_cnt;

// ---------------- helpers ----------------
__device__ __forceinline__ uint32_t s2u(const void* p){
    uint32_t a;
    asm("{ .reg .u64 t; cvta.to.shared.u64 t, %1; cvt.u32.u64 %0, t; }" : "=r"(a) : "l"(p));
    return a;
}
__device__ __forceinline__ void cpa16(uint32_t d, const void* g){
    asm volatile("cp.async.cg.shared.global [%0], [%1], 16;\n" :: "r"(d), "l"(g));
}
__device__ __forceinline__ void cpa_commit(){ asm volatile("cp.async.commit_group;\n" ::); }
template<int N> __device__ __forceinline__ void cpa_wait(){ asm volatile("cp.async.wait_group %0;\n" :: "n"(N)); }

__device__ __forceinline__ void ldsm4(uint32_t r[4], uint32_t a){
    asm volatile("ldmatrix.sync.aligned.m8n8.x4.shared.b16 {%0,%1,%2,%3}, [%4];"
        : "=r"(r[0]), "=r"(r[1]), "=r"(r[2]), "=r"(r[3]) : "r"(a));
}
__device__ __forceinline__ void mma_bf16(float c[4], const uint32_t a[4], const uint32_t b[2]){
    asm volatile("mma.sync.aligned.m16n8k16.row.col.f32.bf16.bf16.f32 "
        "{%0,%1,%2,%3},{%4,%5,%6,%7},{%8,%9},{%0,%1,%2,%3};\n"
        : "+f"(c[0]), "+f"(c[1]), "+f"(c[2]), "+f"(c[3])
        : "r"(a[0]), "r"(a[1]), "r"(a[2]), "r"(a[3]), "r"(b[0]), "r"(b[1]));
}
// device-wide barrier: cumulative counter, release-arrive + acquire-spin
__device__ __forceinline__ void gsync(unsigned target){
    __syncthreads();
    if (threadIdx.x == 0){
        asm volatile("red.release.gpu.global.add.u32 [%0], 1;\n" :: "l"(&g_cnt) : "memory");
        unsigned v;
        do {
            asm volatile("ld.acquire.gpu.global.u32 %0, [%1];\n" : "=r"(v) : "l"(&g_cnt) : "memory");
        } while (v < target);
    }
    __syncthreads();
}

// ---------------- HMMA GEMM core: D[64 x BN] = A[64 x 1024] · B[BN x 1024]^T ----------------
// bf16x3 (AhBh + AhBl + AlBh), fp32 acc. SW128-swizzled 128B-row SMEM tiles, 16 k-stages
// of 64 halves, NS-slot cp.async.cg ring, ldmatrix.x4 fragment loads.
// 128 threads = 4 warps in 2x2; warp tile 32 x (BN/2).
template<int BN, int NS>
__device__ __forceinline__ void gemm_hmma(uint32_t st0,
    const bf16* __restrict__ Ahi, const bf16* __restrict__ Alo,
    const bf16* __restrict__ Bhi, const bf16* __restrict__ Blo,
    float acc[2][BN/16][4])
{
    constexpr uint32_t AB = 64*128, BB = (uint32_t)BN*128, STG = 2*(AB+BB);
    const int tid = threadIdx.x;
    const int lane = tid & 31, wid = tid >> 5;
    const int wm = wid >> 1, wn = wid & 1;
    const int lr = lane & 15, lc = lane >> 4;

    auto lds = [&](int s){
        uint32_t sb = st0 + (uint32_t)(s % NS)*STG;
        int k0 = s*64;
        #pragma unroll
        for (int i = 0; i < 4; ++i){                 // A: 64 rows x 8 chunks(16B)
            int c = tid + i*128;
            int row = c >> 3, kk = c & 7;
            uint32_t off = (uint32_t)(row*128 + kk*16);
            uint32_t sw = off ^ ((off >> 3) & 0x70);
            size_t go = (size_t)row*1024 + k0 + kk*8;
            cpa16(sb + sw, Ahi + go);
            cpa16(sb + AB + sw, Alo + go);
        }
        #pragma unroll
        for (int i = 0; i < BN/16; ++i){             // B: BN rows x 8 chunks
            int c = tid + i*128;
            int row = c >> 3, kk = c & 7;
            uint32_t off = (uint32_t)(row*128 + kk*16);
            uint32_t sw = off ^ ((off >> 3) & 0x70);
            size_t go = (size_t)row*1024 + k0 + kk*8;
            cpa16(sb + 2*AB + sw, Bhi + go);
            cpa16(sb + 2*AB + BB + sw, Blo + go);
        }
        cpa_commit();
    };

    #pragma unroll
    for (int s = 0; s < NS-1; ++s) lds(s);

    #pragma unroll 1
    for (int s = 0; s < 16; ++s){
        if (s + NS - 1 < 16) lds(s + NS - 1);
        int ahead = ((s + NS < 16) ? (s + NS) : 16) - (s + 1);
        if (ahead <= 0) cpa_wait<0>();
        else if (ahead == 1) cpa_wait<1>();
        else cpa_wait<2>();
        __syncthreads();
        uint32_t sb = st0 + (uint32_t)(s % NS)*STG;
        #pragma unroll
        for (int k16 = 0; k16 < 4; ++k16){
            uint32_t ah[2][4], al[2][4];
            #pragma unroll
            for (int mf = 0; mf < 2; ++mf){
                uint32_t off = (uint32_t)((wm*32 + mf*16 + lr)*128 + k16*32 + lc*16);
                uint32_t sw = off ^ ((off >> 3) & 0x70);
                ldsm4(ah[mf], sb + sw);
                ldsm4(al[mf], sb + AB + sw);
            }
            #pragma unroll
            for (int j = 0; j < BN/32; ++j){
                uint32_t bh4[4], bl4[4];
                uint32_t off = (uint32_t)((wn*(BN/2) + j*16 + lr)*128 + k16*32 + lc*16);
                uint32_t sw = off ^ ((off >> 3) & 0x70);
                ldsm4(bh4, sb + 2*AB + sw);
                ldsm4(bl4, sb + 2*AB + BB + sw);
                #pragma unroll
                for (int hh = 0; hh < 2; ++hh){
                    uint32_t b_h[2] = {bh4[hh], bh4[2+hh]};
                    uint32_t b_l[2] = {bl4[hh], bl4[2+hh]};
                    const int nf = j*2 + hh;
                    #pragma unroll
                    for (int mf = 0; mf < 2; ++mf){
                        mma_bf16(acc[mf][nf], ah[mf], b_h);
                        mma_bf16(acc[mf][nf], ah[mf], b_l);
                        mma_bf16(acc[mf][nf], al[mf], b_h);
                    }
                }
            }
        }
        __syncthreads();
    }
}

// ---------------- prep kernels ----------------
__global__ void k_split_sel(const float* __restrict__ src, int sel, size_t off, size_t n){
    bf16 *hi, *lo;
    if (sel == 0){ hi = g_Whi; lo = g_Wlo; }
    else if (sel == 1){ hi = g_Uhi; lo = g_Ulo; }
    else { hi = g_xhi; lo = g_xlo; }
    size_t i = (size_t)blockIdx.x*blockDim.x + threadIdx.x;
    size_t stp = (size_t)gridDim.x*blockDim.x;
    for (; i < n; i += stp){
        float v = src[i];
        bf16 h = __float2bfloat16(v);
        hi[off+i] = h;
        lo[off+i] = __float2bfloat16(v - __bfloat162float(h));
    }
}

__global__ void k_init_h(const float* __restrict__ h0){
    int i = blockIdx.x*blockDim.x + threadIdx.x;
    if (i == 0) g_cnt = 0;               // reset grid barrier each launch (replay-safe)
    if (i < L_*BH){
        float v = h0[i];
        g_h[0][i] = v;
        bf16 h = __float2bfloat16(v);
        g_hhi[0][i] = h;
        g_hlo[0][i] = __float2bfloat16(v - __bfloat162float(h));
    }
}

#define STG64 (2*(64*128 + 64*128))      // 32 KB per stage (BN=64, hi+lo A and B)
#define GEMM_SMEM (3*STG64)              // 96 KB, 3-slot ring

// ---------------- input projection GEMM: g_gx = x·W^T + b ----------------
// grid (96, T): x = ny(16) + 16*gl(6)  -> same-t CTAs adjacent => x[t] L2-broadcast.
__global__ void __launch_bounds__(128,2) k_gemm_input(const float* __restrict__ bz,
        const float* __restrict__ br, const float* __restrict__ bhb){
    extern __shared__ __align__(1024) char dsm[];
    uint32_t st0 = s2u(dsm);
    const int ny = blockIdx.x & 15, gl = blockIdx.x >> 4;
    const int t = blockIdx.y;

    float acc[2][4][4] = {};
    gemm_hmma<64,3>(st0,
        g_xhi + (size_t)t*B_*I_, g_xlo + (size_t)t*B_*I_,
        g_Whi + ((size_t)gl*H_ + (size_t)ny*64)*I_,
        g_Wlo + ((size_t)gl*H_ + (size_t)ny*64)*I_, acc);

    const int gate = gl >> 1, l = gl & 1;
    const float* bias = (gate == 0) ? bz : ((gate == 1) ? br : bhb);
    float* dst = g_gx + ((size_t)gl*T_ + t)*BH;
    const int lane = threadIdx.x & 31, wid = threadIdx.x >> 5;
    const int wm = wid >> 1, wn = wid & 1, gq = lane >> 2, q = lane & 3;
    #pragma unroll
    for (int mf = 0; mf < 2; ++mf)
    #pragma unroll
    for (int nf = 0; nf < 4; ++nf)
    #pragma unroll
    for (int e = 0; e < 4; ++e){
        int row = wm*32 + mf*16 + gq + ((e>>1)<<3);          // batch
        int col = ny*64 + wn*32 + nf*8 + q*2 + (e&1);        // hidden
        dst[(size_t)row*H_ + col] = acc[mf][nf][e] + bias[l*H_ + col];
    }
}

// ---------------- persistent recurrence: 64 CTAs x 128 threads ----------------
// phase A (64 jobs): c = gate*32 + l*16 + ny -> z/r tile [b64 x h64]
// phase B (32 jobs): c = l*16 + ny           -> hh + GRU update
__global__ void __launch_bounds__(128,1) k_recur(float* __restrict__ out){
    extern __shared__ __align__(1024) char dsm[];
    uint32_t st0 = s2u(dsm);
    const int c = blockIdx.x;
    const int lane = threadIdx.x & 31, wid = threadIdx.x >> 5;
    const int wm = wid >> 1, wn = wid & 1, gq = lane >> 2, q = lane & 3;

    const int gate = c >> 5, l = (c >> 4) & 1, ny = c & 15;
    const int lB = (c >> 4) & 1, nyB = c & 15;               // valid when c < 32

    const bf16* UAhi = g_Uhi + ((size_t)(gate*L_ + l)*H_ + (size_t)ny*64)*H_;
    const bf16* UAlo = g_Ulo + ((size_t)(gate*L_ + l)*H_ + (size_t)ny*64)*H_;
    const bf16* UBhi = g_Uhi + ((size_t)(2*L_ + lB)*H_ + (size_t)nyB*64)*H_;
    const bf16* UBlo = g_Ulo + ((size_t)(2*L_ + lB)*H_ + (size_t)nyB*64)*H_;

    unsigned target = 0;

    #pragma unroll 1
    for (int t = 0; t < T_; ++t){
        const int cur = t & 1, nxt = cur ^ 1;

        // ---- phase A: z (gate 0) / r (gate 1), both layers ----
        {
            float acc[2][4][4] = {};
            gemm_hmma<64,3>(st0, g_hhi[cur] + l*BH, g_hlo[cur] + l*BH, UAhi, UAlo, acc);
            const float* gx = g_gx + ((size_t)(gate*L_ + l)*T_ + t)*BH;
            #pragma unroll
            for (int mf = 0; mf < 2; ++mf)
            #pragma unroll
            for (int nf = 0; nf < 4; ++nf)
            #pragma unroll
            for (int e = 0; e < 4; ++e){
                int row = wm*32 + mf*16 + gq + ((e>>1)<<3);
                int col = ny*64 + wn*32 + nf*8 + q*2 + (e&1);
                int idx = l*BH + row*H_ + col;
                float pre = acc[mf][nf][e] + gx[(size_t)row*H_ + col];
                float sg = 1.0f/(1.0f + expf(-pre));
                if (gate == 0){
                    g_z[idx] = sg;
                } else {
                    float rh = sg * g_h[cur][idx];
                    bf16 hb = __float2bfloat16(rh);
                    g_rhhi[idx] = hb;
                    g_rhlo[idx] = __float2bfloat16(rh - __bfloat162float(hb));
                }
            }
        }
        target += RCTAS; gsync(target);

        // ---- phase B: hh + GRU update ----
        if (c < 32){
            float acc[2][4][4] = {};
            gemm_hmma<64,3>(st0, g_rhhi + lB*BH, g_rhlo + lB*BH, UBhi, UBlo, acc);
            const float* gx = g_gx + ((size_t)(2*L_ + lB)*T_ + t)*BH;
            #pragma unroll
            for (int mf = 0; mf < 2; ++mf)
            #pragma unroll
            for (int nf = 0; nf < 4; ++nf)
            #pragma unroll
            for (int e = 0; e < 4; ++e){
                int row = wm*32 + mf*16 + gq + ((e>>1)<<3);
                int col = nyB*64 + wn*32 + nf*8 + q*2 + (e&1);
                int idx = lB*BH + row*H_ + col;
                float hh = tanhf(acc[mf][nf][e] + gx[(size_t)row*H_ + col]);
                float z  = g_z[idx];
                float ho = g_h[cur][idx];
                float hn = ho + z*(hh - ho);
                g_h[nxt][idx] = hn;
                bf16 hb = __float2bfloat16(hn);
                g_hhi[nxt][idx] = hb;
                g_hlo[nxt][idx] = __float2bfloat16(hn - __bfloat162float(hb));
                if (lB == 1) out[((size_t)t*B_ + row)*H_ + col] = hn;
            }
        }
        target += RCTAS; gsync(target);
    }
}

__global__ void k_final(float* __restrict__ dst){
    int i = blockIdx.x*blockDim.x + threadIdx.x;
    if (i < L_*BH) dst[i] = g_h[0][i];   // T_=512 even -> final state in buffer 0
}

// ---------------- launch ----------------
extern "C" void kernel_launch(void* const* d_in, const int* in_sizes, int n_in,
                              void* d_out, int out_size){
    cudaStream_t s = cudaStreamPerThread;
    const float* x  = (const float*)d_in[0];
    const float* h0 = (const float*)d_in[1];
    const float* Wz = (const float*)d_in[2];
    const float* Uz = (const float*)d_in[3];
    const float* bz = (const float*)d_in[4];
    const float* Wr = (const float*)d_in[5];
    const float* Ur = (const float*)d_in[6];
    const float* br = (const float*)d_in[7];
    const float* Wh = (const float*)d_in[8];
    const float* Uh = (const float*)d_in[9];
    const float* bh = (const float*)d_in[10];
    float* out = (float*)d_out;

    cudaFuncSetAttribute(k_gemm_input, cudaFuncAttributeMaxDynamicSharedMemorySize, GEMM_SMEM);
    cudaFuncSetAttribute(k_recur,      cudaFuncAttributeMaxDynamicSharedMemorySize, GEMM_SMEM);

    const size_t nW = (size_t)L_*H_*I_;
    // W splits + x split + h init first, so k_gemm_input is launch #6 (ncu -s 5 -c 1 captures it)
    k_split_sel<<<1024, 256, 0, s>>>(Wz, 0, 0,    nW);
    k_split_sel<<<1024, 256, 0, s>>>(Wr, 0, nW,   nW);
    k_split_sel<<<1024, 256, 0, s>>>(Wh, 0, 2*nW, nW);
    k_split_sel<<<2048, 256, 0, s>>>(x,  2, 0, (size_t)T_*B_*I_);
    k_init_h<<<(L_*BH + 255)/256, 256, 0, s>>>(h0);

    k_gemm_input<<<dim3(96, T_), 128, GEMM_SMEM, s>>>(bz, br, bh);

    k_split_sel<<<1024, 256, 0, s>>>(Uz, 1, 0,    nW);
    k_split_sel<<<1024, 256, 0, s>>>(Ur, 1, nW,   nW);
    k_split_sel<<<1024, 256, 0, s>>>(Uh, 1, 2*nW, nW);

    // whole recurrence in ONE persistent kernel (2 grid barriers per step)
    k_recur<<<RCTAS, 128, GEMM_SMEM, s>>>(out);

    k_final<<<(L_*BH + 255)/256, 256, 0, s>>>(out + (size_t)T_*B_*H_);
}

// round 12
// speedup vs baseline: 1.4848x; 1.4848x over previous
#include <cuda_runtime.h>
#include <cuda_bf16.h>
#include <math.h>
#include <stdint.h>

#define T_ 512
#define B_ 64
#define I_ 1024
#define H_ 1024
#define L_ 2
#define BH (B_*H_)
#define RCTAS 128

typedef __nv_bfloat16 bf16;

// ---------------- static device scratch ----------------
__device__ __align__(256) float g_gx[(size_t)3*L_*T_*B_*H_];
__device__ __align__(256) bf16 g_Whi[(size_t)3*L_*H_*I_], g_Wlo[(size_t)3*L_*H_*I_];
__device__ __align__(256) bf16 g_Uhi[(size_t)3*L_*H_*H_], g_Ulo[(size_t)3*L_*H_*H_];
__device__ __align__(256) bf16 g_xhi[(size_t)T_*B_*I_], g_xlo[(size_t)T_*B_*I_];
__device__ __align__(256) float g_h[2][L_*BH];
__device__ __align__(256) bf16 g_hhi[2][L_*BH], g_hlo[2][L_*BH];
__device__ __align__(256) float g_z[L_*BH];
__device__ __align__(256) bf16 g_rhhi[L_*BH], g_rhlo[L_*BH];
__device__ unsigned g_cnt;

// ---------------- helpers ----------------
__device__ __forceinline__ uint32_t s2u(const void* p){
    uint32_t a;
    asm("{ .reg .u64 t; cvta.to.shared.u64 t, %1; cvt.u32.u64 %0, t; }" : "=r"(a) : "l"(p));
    return a;
}
__device__ __forceinline__ void cpa16(uint32_t d, const void* g){
    asm volatile("cp.async.cg.shared.global [%0], [%1], 16;\n" :: "r"(d), "l"(g));
}
__device__ __forceinline__ void cpa_commit(){ asm volatile("cp.async.commit_group;\n" ::); }
template<int N> __device__ __forceinline__ void cpa_wait(){ asm volatile("cp.async.wait_group %0;\n" :: "n"(N)); }

__device__ __forceinline__ void ldsm4(uint32_t r[4], uint32_t a){
    asm volatile("ldmatrix.sync.aligned.m8n8.x4.shared.b16 {%0,%1,%2,%3}, [%4];"
        : "=r"(r[0]), "=r"(r[1]), "=r"(r[2]), "=r"(r[3]) : "r"(a));
}
__device__ __forceinline__ void mma_bf16(float c[4], const uint32_t a[4], const uint32_t b[2]){
    asm volatile("mma.sync.aligned.m16n8k16.row.col.f32.bf16.bf16.f32 "
        "{%0,%1,%2,%3},{%4,%5,%6,%7},{%8,%9},{%0,%1,%2,%3};\n"
        : "+f"(c[0]), "+f"(c[1]), "+f"(c[2]), "+f"(c[3])
        : "r"(a[0]), "r"(a[1]), "r"(a[2]), "r"(a[3]), "r"(b[0]), "r"(b[1]));
}
// device-wide barrier: cumulative counter, release-arrive + acquire-spin
__device__ __forceinline__ void gsync(unsigned target){
    __syncthreads();
    if (threadIdx.x == 0){
        asm volatile("red.release.gpu.global.add.u32 [%0], 1;\n" :: "l"(&g_cnt) : "memory");
        unsigned v;
        do {
            asm volatile("ld.acquire.gpu.global.u32 %0, [%1];\n" : "=r"(v) : "l"(&g_cnt) : "memory");
        } while (v < target);
    }
    __syncthreads();
}

// ---------------- HMMA GEMM core: D[64 x BN] = A[64 x 1024] · B[BN x 1024]^T ----------------
// bf16x3 (AhBh + AhBl + AlBh), fp32 acc. SW128-swizzled 128B-row SMEM tiles, 16 k-stages
// of 64 halves, NS-slot cp.async.cg ring, ldmatrix.x4 fragment loads.
// 128 threads = 4 warps in 2x2; warp tile 32 x (BN/2).
template<int BN, int NS>
__device__ __forceinline__ void gemm_hmma(uint32_t st0,
    const bf16* __restrict__ Ahi, const bf16* __restrict__ Alo,
    const bf16* __restrict__ Bhi, const bf16* __restrict__ Blo,
    float acc[2][BN/16][4])
{
    constexpr uint32_t AB = 64*128, BB = (uint32_t)BN*128, STG = 2*(AB+BB);
    const int tid = threadIdx.x;
    const int lane = tid & 31, wid = tid >> 5;
    const int wm = wid >> 1, wn = wid & 1;
    const int lr = lane & 15, lc = lane >> 4;

    auto lds = [&](int s){
        uint32_t sb = st0 + (uint32_t)(s % NS)*STG;
        int k0 = s*64;
        #pragma unroll
        for (int i = 0; i < 4; ++i){                 // A: 64 rows x 8 chunks(16B)
            int c = tid + i*128;
            int row = c >> 3, kk = c & 7;
            uint32_t off = (uint32_t)(row*128 + kk*16);
            uint32_t sw = off ^ ((off >> 3) & 0x70);
            size_t go = (size_t)row*1024 + k0 + kk*8;
            cpa16(sb + sw, Ahi + go);
            cpa16(sb + AB + sw, Alo + go);
        }
        #pragma unroll
        for (int i = 0; i < BN/16; ++i){             // B: BN rows x 8 chunks
            int c = tid + i*128;
            int row = c >> 3, kk = c & 7;
            uint32_t off = (uint32_t)(row*128 + kk*16);
            uint32_t sw = off ^ ((off >> 3) & 0x70);
            size_t go = (size_t)row*1024 + k0 + kk*8;
            cpa16(sb + 2*AB + sw, Bhi + go);
            cpa16(sb + 2*AB + BB + sw, Blo + go);
        }
        cpa_commit();
    };

    #pragma unroll
    for (int s = 0; s < NS-1; ++s) lds(s);

    #pragma unroll 1
    for (int s = 0; s < 16; ++s){
        if (s + NS - 1 < 16) lds(s + NS - 1);
        int ahead = ((s + NS < 16) ? (s + NS) : 16) - (s + 1);
        if (ahead <= 0) cpa_wait<0>();
        else if (ahead == 1) cpa_wait<1>();
        else cpa_wait<2>();
        __syncthreads();
        uint32_t sb = st0 + (uint32_t)(s % NS)*STG;
        #pragma unroll
        for (int k16 = 0; k16 < 4; ++k16){
            uint32_t ah[2][4], al[2][4];
            #pragma unroll
            for (int mf = 0; mf < 2; ++mf){
                uint32_t off = (uint32_t)((wm*32 + mf*16 + lr)*128 + k16*32 + lc*16);
                uint32_t sw = off ^ ((off >> 3) & 0x70);
                ldsm4(ah[mf], sb + sw);
                ldsm4(al[mf], sb + AB + sw);
            }
            #pragma unroll
            for (int j = 0; j < BN/32; ++j){
                uint32_t bh4[4], bl4[4];
                uint32_t off = (uint32_t)((wn*(BN/2) + j*16 + lr)*128 + k16*32 + lc*16);
                uint32_t sw = off ^ ((off >> 3) & 0x70);
                ldsm4(bh4, sb + 2*AB + sw);
                ldsm4(bl4, sb + 2*AB + BB + sw);
                #pragma unroll
                for (int hh = 0; hh < 2; ++hh){
                    uint32_t b_h[2] = {bh4[hh], bh4[2+hh]};
                    uint32_t b_l[2] = {bl4[hh], bl4[2+hh]};
                    const int nf = j*2 + hh;
                    #pragma unroll
                    for (int mf = 0; mf < 2; ++mf){
                        mma_bf16(acc[mf][nf], ah[mf], b_h);
                        mma_bf16(acc[mf][nf], ah[mf], b_l);
                        mma_bf16(acc[mf][nf], al[mf], b_h);
                    }
                }
            }
        }
        __syncthreads();
    }
}

// ---------------- prep kernels ----------------
__global__ void k_split_sel(const float* __restrict__ src, int sel, size_t off, size_t n){
    bf16 *hi, *lo;
    if (sel == 0){ hi = g_Whi; lo = g_Wlo; }
    else if (sel == 1){ hi = g_Uhi; lo = g_Ulo; }
    else { hi = g_xhi; lo = g_xlo; }
    size_t i = (size_t)blockIdx.x*blockDim.x + threadIdx.x;
    size_t stp = (size_t)gridDim.x*blockDim.x;
    for (; i < n; i += stp){
        float v = src[i];
        bf16 h = __float2bfloat16(v);
        hi[off+i] = h;
        lo[off+i] = __float2bfloat16(v - __bfloat162float(h));
    }
}

__global__ void k_init_h(const float* __restrict__ h0){
    int i = blockIdx.x*blockDim.x + threadIdx.x;
    if (i == 0) g_cnt = 0;               // reset grid barrier each launch (replay-safe)
    if (i < L_*BH){
        float v = h0[i];
        g_h[0][i] = v;
        bf16 h = __float2bfloat16(v);
        g_hhi[0][i] = h;
        g_hlo[0][i] = __float2bfloat16(v - __bfloat162float(h));
    }
}

#define STG64 (2*(64*128 + 64*128))      // 32 KB per stage (BN=64)
#define STG32 (2*(64*128 + 32*128))      // 24 KB per stage (BN=32)
#define PROJ_SMEM  (3*STG64)             // 96 KB
#define RECUR_SMEM (3*STG32)             // 72 KB -> all 128 CTAs co-resident

// ---------------- input projection GEMM: g_gx = x·W^T + b ----------------
// grid (96, T): x = ny(16) + 16*gl(6) -> same-t CTAs adjacent => x[t] L2-broadcast,
// W tiles (24MB hi+lo) L2-resident across the whole kernel.
__global__ void __launch_bounds__(128,2) k_gemm_input(const float* __restrict__ bz,
        const float* __restrict__ br, const float* __restrict__ bhb){
    extern __shared__ __align__(1024) char dsm[];
    uint32_t st0 = s2u(dsm);
    const int ny = blockIdx.x & 15, gl = blockIdx.x >> 4;
    const int t = blockIdx.y;

    float acc[2][4][4] = {};
    gemm_hmma<64,3>(st0,
        g_xhi + (size_t)t*B_*I_, g_xlo + (size_t)t*B_*I_,
        g_Whi + ((size_t)gl*H_ + (size_t)ny*64)*I_,
        g_Wlo + ((size_t)gl*H_ + (size_t)ny*64)*I_, acc);

    const int gate = gl >> 1, l = gl & 1;
    const float* bias = (gate == 0) ? bz : ((gate == 1) ? br : bhb);
    float* dst = g_gx + ((size_t)gl*T_ + t)*BH;
    const int lane = threadIdx.x & 31, wid = threadIdx.x >> 5;
    const int wm = wid >> 1, wn = wid & 1, gq = lane >> 2, q = lane & 3;
    #pragma unroll
    for (int mf = 0; mf < 2; ++mf)
    #pragma unroll
    for (int nf = 0; nf < 4; ++nf)
    #pragma unroll
    for (int e = 0; e < 4; ++e){
        int row = wm*32 + mf*16 + gq + ((e>>1)<<3);          // batch
        int col = ny*64 + wn*32 + nf*8 + q*2 + (e&1);        // hidden
        dst[(size_t)row*H_ + col] = acc[mf][nf][e] + bias[l*H_ + col];
    }
}

// ---------------- persistent recurrence: 128 CTAs x 128 threads ----------------
// phase A (128 jobs): c = gate*64 + l*32 + ny -> z/r tile [b64 x h32]
// phase B  (64 jobs): c = l*32 + ny           -> hh + GRU update
__global__ void __launch_bounds__(128,1) k_recur(float* __restrict__ out){
    extern __shared__ __align__(1024) char dsm[];
    uint32_t st0 = s2u(dsm);
    const int c = blockIdx.x;
    const int lane = threadIdx.x & 31, wid = threadIdx.x >> 5;
    const int wm = wid >> 1, wn = wid & 1, gq = lane >> 2, q = lane & 3;

    const int gate = c >> 6, l = (c >> 5) & 1, ny = c & 31;
    const int lB = (c >> 5) & 1, nyB = c & 31;               // valid when c < 64

    const bf16* UAhi = g_Uhi + ((size_t)(gate*L_ + l)*H_ + (size_t)ny*32)*H_;
    const bf16* UAlo = g_Ulo + ((size_t)(gate*L_ + l)*H_ + (size_t)ny*32)*H_;
    const bf16* UBhi = g_Uhi + ((size_t)(2*L_ + lB)*H_ + (size_t)nyB*32)*H_;
    const bf16* UBlo = g_Ulo + ((size_t)(2*L_ + lB)*H_ + (size_t)nyB*32)*H_;

    unsigned target = 0;

    #pragma unroll 1
    for (int t = 0; t < T_; ++t){
        const int cur = t & 1, nxt = cur ^ 1;

        // ---- phase A: z (gate 0) / r (gate 1), both layers ----
        {
            float acc[2][2][4] = {};
            gemm_hmma<32,3>(st0, g_hhi[cur] + l*BH, g_hlo[cur] + l*BH, UAhi, UAlo, acc);
            const float* gx = g_gx + ((size_t)(gate*L_ + l)*T_ + t)*BH;
            #pragma unroll
            for (int mf = 0; mf < 2; ++mf)
            #pragma unroll
            for (int nf = 0; nf < 2; ++nf)
            #pragma unroll
            for (int e = 0; e < 4; ++e){
                int row = wm*32 + mf*16 + gq + ((e>>1)<<3);
                int col = ny*32 + wn*16 + nf*8 + q*2 + (e&1);
                int idx = l*BH + row*H_ + col;
                float pre = acc[mf][nf][e] + gx[(size_t)row*H_ + col];
                float sg = 1.0f/(1.0f + expf(-pre));
                if (gate == 0){
                    g_z[idx] = sg;
                } else {
                    float rh = sg * g_h[cur][idx];
                    bf16 hb = __float2bfloat16(rh);
                    g_rhhi[idx] = hb;
                    g_rhlo[idx] = __float2bfloat16(rh - __bfloat162float(hb));
                }
            }
        }
        target += RCTAS; gsync(target);

        // ---- phase B: hh + GRU update ----
        if (c < 64){
            float acc[2][2][4] = {};
            gemm_hmma<32,3>(st0, g_rhhi + lB*BH, g_rhlo + lB*BH, UBhi, UBlo, acc);
            const float* gx = g_gx + ((size_t)(2*L_ + lB)*T_ + t)*BH;
            #pragma unroll
            for (int mf = 0; mf < 2; ++mf)
            #pragma unroll
            for (int nf = 0; nf < 2; ++nf)
            #pragma unroll
            for (int e = 0; e < 4; ++e){
                int row = wm*32 + mf*16 + gq + ((e>>1)<<3);
                int col = nyB*32 + wn*16 + nf*8 + q*2 + (e&1);
                int idx = lB*BH + row*H_ + col;
                float hh = tanhf(acc[mf][nf][e] + gx[(size_t)row*H_ + col]);
                float z  = g_z[idx];
                float ho = g_h[cur][idx];
                float hn = ho + z*(hh - ho);
                g_h[nxt][idx] = hn;
                bf16 hb = __float2bfloat16(hn);
                g_hhi[nxt][idx] = hb;
                g_hlo[nxt][idx] = __float2bfloat16(hn - __bfloat162float(hb));
                if (lB == 1) out[((size_t)t*B_ + row)*H_ + col] = hn;
            }
        }
        target += RCTAS; gsync(target);
    }
}

__global__ void k_final(float* __restrict__ dst){
    int i = blockIdx.x*blockDim.x + threadIdx.x;
    if (i < L_*BH) dst[i] = g_h[0][i];   // T_=512 even -> final state in buffer 0
}

// ---------------- launch ----------------
extern "C" void kernel_launch(void* const* d_in, const int* in_sizes, int n_in,
                              void* d_out, int out_size){
    cudaStream_t s = cudaStreamPerThread;
    const float* x  = (const float*)d_in[0];
    const float* h0 = (const float*)d_in[1];
    const float* Wz = (const float*)d_in[2];
    const float* Uz = (const float*)d_in[3];
    const float* bz = (const float*)d_in[4];
    const float* Wr = (const float*)d_in[5];
    const float* Ur = (const float*)d_in[6];
    const float* br = (const float*)d_in[7];
    const float* Wh = (const float*)d_in[8];
    const float* Uh = (const float*)d_in[9];
    const float* bh = (const float*)d_in[10];
    float* out = (float*)d_out;

    cudaFuncSetAttribute(k_gemm_input, cudaFuncAttributeMaxDynamicSharedMemorySize, PROJ_SMEM);
    cudaFuncSetAttribute(k_recur,      cudaFuncAttributeMaxDynamicSharedMemorySize, RECUR_SMEM);

    const size_t nW = (size_t)L_*H_*I_;
    k_split_sel<<<1024, 256, 0, s>>>(Wz, 0, 0,    nW);
    k_split_sel<<<1024, 256, 0, s>>>(Wr, 0, nW,   nW);
    k_split_sel<<<1024, 256, 0, s>>>(Wh, 0, 2*nW, nW);
    k_split_sel<<<2048, 256, 0, s>>>(x,  2, 0, (size_t)T_*B_*I_);
    k_init_h<<<(L_*BH + 255)/256, 256, 0, s>>>(h0);

    k_gemm_input<<<dim3(96, T_), 128, PROJ_SMEM, s>>>(bz, br, bh);

    k_split_sel<<<1024, 256, 0, s>>>(Uz, 1, 0,    nW);
    k_split_sel<<<1024, 256, 0, s>>>(Ur, 1, nW,   nW);
    k_split_sel<<<1024, 256, 0, s>>>(Uh, 1, 2*nW, nW);

    // whole recurrence in ONE persistent kernel (2 grid barriers per step)
    k_recur<<<RCTAS, 128, RECUR_SMEM, s>>>(out);

    k_final<<<(L_*BH + 255)/256, 256, 0, s>>>(out + (size_t)T_*B_*H_);
}

// round 13
// speedup vs baseline: 1.9227x; 1.2949x over previous
#include <cuda_runtime.h>
#include <cuda_bf16.h>
#include <math.h>
#include <stdint.h>

#define T_ 512
#define B_ 64
#define I_ 1024
#define H_ 1024
#define L_ 2
#define BH (B_*H_)
#define RCTAS 128

typedef __nv_bfloat16 bf16;

// ---------------- static device scratch ----------------
__device__ __align__(256) float g_gx[(size_t)3*L_*T_*B_*H_];
__device__ __align__(256) bf16 g_Whi[(size_t)3*L_*H_*I_], g_Wlo[(size_t)3*L_*H_*I_];
__device__ __align__(256) bf16 g_Uhi[(size_t)3*L_*H_*H_], g_Ulo[(size_t)3*L_*H_*H_];
__device__ __align__(256) bf16 g_xhi[(size_t)T_*B_*I_], g_xlo[(size_t)T_*B_*I_];
__device__ __align__(256) float g_h[2][L_*BH];
__device__ __align__(256) bf16 g_hhi[2][L_*BH], g_hlo[2][L_*BH];
__device__ __align__(256) float g_z[L_*BH];
__device__ __align__(256) bf16 g_rhhi[L_*BH], g_rhlo[L_*BH];
__device__ unsigned g_cnt;

// ---------------- helpers ----------------
__device__ __forceinline__ uint32_t s2u(const void* p){
    uint32_t a;
    asm("{ .reg .u64 t; cvta.to.shared.u64 t, %1; cvt.u32.u64 %0, t; }" : "=r"(a) : "l"(p));
    return a;
}
__device__ __forceinline__ void cpa16(uint32_t d, const void* g){
    asm volatile("cp.async.cg.shared.global [%0], [%1], 16;\n" :: "r"(d), "l"(g));
}
__device__ __forceinline__ void cpa_commit(){ asm volatile("cp.async.commit_group;\n" ::); }
template<int N> __device__ __forceinline__ void cpa_wait(){ asm volatile("cp.async.wait_group %0;\n" :: "n"(N)); }

__device__ __forceinline__ void ldsm4(uint32_t r[4], uint32_t a){
    asm volatile("ldmatrix.sync.aligned.m8n8.x4.shared.b16 {%0,%1,%2,%3}, [%4];"
        : "=r"(r[0]), "=r"(r[1]), "=r"(r[2]), "=r"(r[3]) : "r"(a));
}
__device__ __forceinline__ void ldsm2(uint32_t r[2], uint32_t a){
    asm volatile("ldmatrix.sync.aligned.m8n8.x2.shared.b16 {%0,%1}, [%2];"
        : "=r"(r[0]), "=r"(r[1]) : "r"(a));
}
__device__ __forceinline__ void mma_bf16(float c[4], const uint32_t a[4], const uint32_t b[2]){
    asm volatile("mma.sync.aligned.m16n8k16.row.col.f32.bf16.bf16.f32 "
        "{%0,%1,%2,%3},{%4,%5,%6,%7},{%8,%9},{%0,%1,%2,%3};\n"
        : "+f"(c[0]), "+f"(c[1]), "+f"(c[2]), "+f"(c[3])
        : "r"(a[0]), "r"(a[1]), "r"(a[2]), "r"(a[3]), "r"(b[0]), "r"(b[1]));
}
// device-wide barrier: cumulative counter, release-arrive + acquire-spin
__device__ __forceinline__ void gsync(unsigned target){
    __syncthreads();
    if (threadIdx.x == 0){
        asm volatile("red.release.gpu.global.add.u32 [%0], 1;\n" :: "l"(&g_cnt) : "memory");
        unsigned v;
        do {
            asm volatile("ld.acquire.gpu.global.u32 %0, [%1];\n" : "=r"(v) : "l"(&g_cnt) : "memory");
        } while (v < target);
    }
    __syncthreads();
}

// ---------------- 256-thread HMMA GEMM core: D[64 x BN] = A[64 x 1024]·B[BN x 1024]^T ------
// bf16x3 (AhBh + AhBl + AlBh), fp32 acc. SW128-swizzled 128B-row SMEM, 16 k-stages of 64
// halves, NS-slot cp.async.cg ring, ldmatrix fragment loads.
// 8 warps in a 4x2 grid: warp tile M=16, N=BN/2. acc layout [BN/16][4] per warp.
template<int BN, int NS>
__device__ __forceinline__ void gemm256(uint32_t st0,
    const bf16* __restrict__ Ahi, const bf16* __restrict__ Alo,
    const bf16* __restrict__ Bhi, const bf16* __restrict__ Blo,
    float acc[BN/16][4])
{
    constexpr uint32_t AB = 64*128, BB = (uint32_t)BN*128, STG = 2*(AB+BB);
    const int tid = threadIdx.x;
    const int lane = tid & 31, wid = tid >> 5;
    const int wm = wid & 3, wn = wid >> 2;
    const int lr = lane & 15, lc = lane >> 4;

    auto lds = [&](int s){
        uint32_t sb = st0 + (uint32_t)(s % NS)*STG;
        int k0 = s*64;
        #pragma unroll
        for (int i = 0; i < 2; ++i){                      // A: 512 16B-chunks
            int c = tid + i*256;
            int row = c >> 3, kk = c & 7;
            uint32_t off = (uint32_t)(row*128 + kk*16);
            uint32_t sw = off ^ ((off >> 3) & 0x70);
            size_t go = (size_t)row*1024 + k0 + kk*8;
            cpa16(sb + sw, Ahi + go);
            cpa16(sb + AB + sw, Alo + go);
        }
        #pragma unroll
        for (int i = 0; i < (BN*8 + 255)/256; ++i){       // B: BN*8 chunks
            int c = tid + i*256;
            if ((BN*8) % 256 == 0 || c < BN*8){
                int row = c >> 3, kk = c & 7;
                uint32_t off = (uint32_t)(row*128 + kk*16);
                uint32_t sw = off ^ ((off >> 3) & 0x70);
                size_t go = (size_t)row*1024 + k0 + kk*8;
                cpa16(sb + 2*AB + sw, Bhi + go);
                cpa16(sb + 2*AB + BB + sw, Blo + go);
            }
        }
        cpa_commit();
    };

    #pragma unroll
    for (int s = 0; s < NS-1; ++s) lds(s);

    #pragma unroll 1
    for (int s = 0; s < 16; ++s){
        if (s + NS - 1 < 16) lds(s + NS - 1);
        int ahead = ((s + NS < 16) ? (s + NS) : 16) - (s + 1);
        if (ahead <= 0) cpa_wait<0>();
        else if (ahead == 1) cpa_wait<1>();
        else cpa_wait<2>();
        __syncthreads();
        uint32_t sb = st0 + (uint32_t)(s % NS)*STG;
        #pragma unroll
        for (int k16 = 0; k16 < 4; ++k16){
            uint32_t ah[4], al[4];
            {
                uint32_t off = (uint32_t)((wm*16 + lr)*128 + k16*32 + lc*16);
                uint32_t sw = off ^ ((off >> 3) & 0x70);
                ldsm4(ah, sb + sw);
                ldsm4(al, sb + AB + sw);
            }
            if constexpr (BN >= 32){
                #pragma unroll
                for (int j = 0; j < BN/32; ++j){
                    uint32_t bh4[4], bl4[4];
                    uint32_t off = (uint32_t)((wn*(BN/2) + j*16 + lr)*128 + k16*32 + lc*16);
                    uint32_t sw = off ^ ((off >> 3) & 0x70);
                    ldsm4(bh4, sb + 2*AB + sw);
                    ldsm4(bl4, sb + 2*AB + BB + sw);
                    #pragma unroll
                    for (int hh = 0; hh < 2; ++hh){
                        uint32_t b_h[2] = {bh4[hh], bh4[2+hh]};
                        uint32_t b_l[2] = {bl4[hh], bl4[2+hh]};
                        mma_bf16(acc[j*2+hh], ah, b_h);
                        mma_bf16(acc[j*2+hh], ah, b_l);
                        mma_bf16(acc[j*2+hh], al, b_h);
                    }
                }
            } else {   // BN == 16: warp N=8, ldmatrix.x2 (lanes 0-15 give mat0=k0-7, mat1=k8-15)
                uint32_t bh2[2], bl2[2];
                uint32_t off = (uint32_t)((wn*8 + (lr & 7))*128 + k16*32 + ((lr >> 3) & 1)*16);
                uint32_t sw = off ^ ((off >> 3) & 0x70);
                ldsm2(bh2, sb + 2*AB + sw);
                ldsm2(bl2, sb + 2*AB + BB + sw);
                mma_bf16(acc[0], ah, bh2);
                mma_bf16(acc[0], ah, bl2);
                mma_bf16(acc[0], al, bh2);
            }
        }
        __syncthreads();
    }
}

// ---------------- prep kernels ----------------
__device__ __forceinline__ void split1(const float* src, bf16* hi, bf16* lo, size_t off, size_t i){
    float v = src[i];
    bf16 h = __float2bfloat16(v);
    hi[off+i] = h;
    lo[off+i] = __float2bfloat16(v - __bfloat162float(h));
}
__global__ void k_split_x(const float* __restrict__ x){
    size_t n = (size_t)T_*B_*I_;
    size_t i = (size_t)blockIdx.x*blockDim.x + threadIdx.x;
    size_t stp = (size_t)gridDim.x*blockDim.x;
    for (; i < n; i += stp) split1(x, g_xhi, g_xlo, 0, i);
}
__global__ void k_split_W(const float* __restrict__ a, const float* __restrict__ b,
                          const float* __restrict__ c){
    const size_t n = (size_t)L_*H_*I_;
    size_t i = (size_t)blockIdx.x*blockDim.x + threadIdx.x;
    size_t stp = (size_t)gridDim.x*blockDim.x;
    for (; i < n; i += stp){
        split1(a, g_Whi, g_Wlo, 0,   i);
        split1(b, g_Whi, g_Wlo, n,   i);
        split1(c, g_Whi, g_Wlo, 2*n, i);
    }
}
__global__ void k_split_U(const float* __restrict__ a, const float* __restrict__ b,
                          const float* __restrict__ c){
    const size_t n = (size_t)L_*H_*H_;
    size_t i = (size_t)blockIdx.x*blockDim.x + threadIdx.x;
    size_t stp = (size_t)gridDim.x*blockDim.x;
    for (; i < n; i += stp){
        split1(a, g_Uhi, g_Ulo, 0,   i);
        split1(b, g_Uhi, g_Ulo, n,   i);
        split1(c, g_Uhi, g_Ulo, 2*n, i);
    }
}
__global__ void k_init_h(const float* __restrict__ h0){
    int i = blockIdx.x*blockDim.x + threadIdx.x;
    if (i == 0) g_cnt = 0;               // reset grid barrier each launch (replay-safe)
    if (i < L_*BH){
        float v = h0[i];
        g_h[0][i] = v;
        bf16 h = __float2bfloat16(v);
        g_hhi[0][i] = h;
        g_hlo[0][i] = __float2bfloat16(v - __bfloat162float(h));
    }
}

#define STG64 (2*(64*128 + 64*128))      // 32 KB per stage (BN=64)
#define STG32 (2*(64*128 + 32*128))      // 24 KB per stage (BN=32)
#define PROJ_SMEM  (3*STG64)             // 96 KB
#define RECUR_SMEM (3*STG32)             // 72 KB -> all 128 CTAs co-resident

// ---------------- input projection GEMM: g_gx = x·W^T + b ----------------
// grid (96, T): x = ny(16) + 16*gl(6) -> same-t CTAs adjacent => x[t] L2-broadcast,
// W tiles (24MB hi+lo) L2-resident across the whole kernel.
__global__ void __launch_bounds__(256,1) k_gemm_input(const float* __restrict__ bz,
        const float* __restrict__ br, const float* __restrict__ bhb){
    extern __shared__ __align__(1024) char dsm[];
    uint32_t st0 = s2u(dsm);
    const int ny = blockIdx.x & 15, gl = blockIdx.x >> 4;
    const int t = blockIdx.y;

    float acc[4][4] = {};
    gemm256<64,3>(st0,
        g_xhi + (size_t)t*B_*I_, g_xlo + (size_t)t*B_*I_,
        g_Whi + ((size_t)gl*H_ + (size_t)ny*64)*I_,
        g_Wlo + ((size_t)gl*H_ + (size_t)ny*64)*I_, acc);

    const int gate = gl >> 1, l = gl & 1;
    const float* bias = (gate == 0) ? bz : ((gate == 1) ? br : bhb);
    float* dst = g_gx + ((size_t)gl*T_ + t)*BH;
    const int lane = threadIdx.x & 31, wid = threadIdx.x >> 5;
    const int wm = wid & 3, wn = wid >> 2, gq = lane >> 2, q = lane & 3;
    #pragma unroll
    for (int nf = 0; nf < 4; ++nf)
    #pragma unroll
    for (int e = 0; e < 4; ++e){
        int row = wm*16 + gq + ((e>>1)<<3);                  // batch
        int col = ny*64 + wn*32 + nf*8 + q*2 + (e&1);        // hidden
        dst[(size_t)row*H_ + col] = acc[nf][e] + bias[l*H_ + col];
    }
}

// ---------------- persistent recurrence: 128 CTAs x 256 threads ----------------
// phase A (128 jobs, BN=32): c = gate*64 + l*32 + ny -> z/r tile [b64 x h32]
// phase B (128 jobs, BN=16): c = l*64 + ny           -> hh tile [b64 x h16] + GRU update
__global__ void __launch_bounds__(256,1) k_recur(float* __restrict__ out){
    extern __shared__ __align__(1024) char dsm[];
    uint32_t st0 = s2u(dsm);
    const int c = blockIdx.x;
    const int lane = threadIdx.x & 31, wid = threadIdx.x >> 5;
    const int wm = wid & 3, wn = wid >> 2, gq = lane >> 2, q = lane & 3;

    const int gate = c >> 6, l = (c >> 5) & 1, ny = c & 31;   // phase A mapping
    const int lB = c >> 6, nyB = c & 63;                      // phase B mapping

    const bf16* UAhi = g_Uhi + ((size_t)(gate*L_ + l)*H_ + (size_t)ny*32)*H_;
    const bf16* UAlo = g_Ulo + ((size_t)(gate*L_ + l)*H_ + (size_t)ny*32)*H_;
    const bf16* UBhi = g_Uhi + ((size_t)(2*L_ + lB)*H_ + (size_t)nyB*16)*H_;
    const bf16* UBlo = g_Ulo + ((size_t)(2*L_ + lB)*H_ + (size_t)nyB*16)*H_;

    unsigned target = 0;

    #pragma unroll 1
    for (int t = 0; t < T_; ++t){
        const int cur = t & 1, nxt = cur ^ 1;

        // ---- phase A: z (gate 0) / r (gate 1), both layers ----
        {
            float acc[2][4] = {};
            gemm256<32,3>(st0, g_hhi[cur] + l*BH, g_hlo[cur] + l*BH, UAhi, UAlo, acc);
            const float* gx = g_gx + ((size_t)(gate*L_ + l)*T_ + t)*BH;
            #pragma unroll
            for (int nf = 0; nf < 2; ++nf)
            #pragma unroll
            for (int e = 0; e < 4; ++e){
                int row = wm*16 + gq + ((e>>1)<<3);
                int col = ny*32 + wn*16 + nf*8 + q*2 + (e&1);
                int idx = l*BH + row*H_ + col;
                float pre = acc[nf][e] + gx[(size_t)row*H_ + col];
                float sg = 1.0f/(1.0f + expf(-pre));
                if (gate == 0){
                    g_z[idx] = sg;
                } else {
                    float rh = sg * g_h[cur][idx];
                    bf16 hb = __float2bfloat16(rh);
                    g_rhhi[idx] = hb;
                    g_rhlo[idx] = __float2bfloat16(rh - __bfloat162float(hb));
                }
            }
        }
        target += RCTAS; gsync(target);

        // ---- phase B: hh + GRU update (all 128 CTAs, BN=16) ----
        {
            float acc[1][4] = {};
            gemm256<16,3>(st0, g_rhhi + lB*BH, g_rhlo + lB*BH, UBhi, UBlo, acc);
            const float* gx = g_gx + ((size_t)(2*L_ + lB)*T_ + t)*BH;
            #pragma unroll
            for (int e = 0; e < 4; ++e){
                int row = wm*16 + gq + ((e>>1)<<3);
                int col = nyB*16 + wn*8 + q*2 + (e&1);
                int idx = lB*BH + row*H_ + col;
                float hh = tanhf(acc[0][e] + gx[(size_t)row*H_ + col]);
                float z  = g_z[idx];
                float ho = g_h[cur][idx];
                float hn = ho + z*(hh - ho);
                g_h[nxt][idx] = hn;
                bf16 hb = __float2bfloat16(hn);
                g_hhi[nxt][idx] = hb;
                g_hlo[nxt][idx] = __float2bfloat16(hn - __bfloat162float(hb));
                if (lB == 1) out[((size_t)t*B_ + row)*H_ + col] = hn;
            }
        }
        target += RCTAS; gsync(target);
    }
}

__global__ void k_final(float* __restrict__ dst){
    int i = blockIdx.x*blockDim.x + threadIdx.x;
    if (i < L_*BH) dst[i] = g_h[0][i];   // T_=512 even -> final state in buffer 0
}

// ---------------- launch ----------------
extern "C" void kernel_launch(void* const* d_in, const int* in_sizes, int n_in,
                              void* d_out, int out_size){
    cudaStream_t s = cudaStreamPerThread;
    const float* x  = (const float*)d_in[0];
    const float* h0 = (const float*)d_in[1];
    const float* Wz = (const float*)d_in[2];
    const float* Uz = (const float*)d_in[3];
    const float* bz = (const float*)d_in[4];
    const float* Wr = (const float*)d_in[5];
    const float* Ur = (const float*)d_in[6];
    const float* br = (const float*)d_in[7];
    const float* Wh = (const float*)d_in[8];
    const float* Uh = (const float*)d_in[9];
    const float* bh = (const float*)d_in[10];
    float* out = (float*)d_out;

    cudaFuncSetAttribute(k_gemm_input, cudaFuncAttributeMaxDynamicSharedMemorySize, PROJ_SMEM);
    cudaFuncSetAttribute(k_recur,      cudaFuncAttributeMaxDynamicSharedMemorySize, RECUR_SMEM);

    // launch order chosen so slot #4 (the one ncu captures) is k_gemm_input
    k_split_x<<<2048, 256, 0, s>>>(x);                                   // 1
    k_split_W<<<1024, 256, 0, s>>>(Wz, Wr, Wh);                          // 2
    k_init_h<<<(L_*BH + 255)/256, 256, 0, s>>>(h0);                      // 3
    k_gemm_input<<<dim3(96, T_), 256, PROJ_SMEM, s>>>(bz, br, bh);       // 4 <- profiled
    k_split_U<<<1024, 256, 0, s>>>(Uz, Ur, Uh);                          // 5
    k_recur<<<RCTAS, 256, RECUR_SMEM, s>>>(out);                         // 6
    k_final<<<(L_*BH + 255)/256, 256, 0, s>>>(out + (size_t)T_*B_*H_);   // 7
}